// round 1
// baseline (speedup 1.0000x reference)
#include <cuda_runtime.h>
#include <cstdint>

// Problem constants
#define M_ROWS (8 * 4096)   // B*N = 32768 rows
#define DIM 1024            // INPUT_DIM == HIDDEN_DIM
#define NH 4                // heads
#define HD 256              // head dim

// Scratch (static device arrays — no allocation allowed)
__device__ float g_Q[M_ROWS * DIM];
__device__ float g_K[M_ROWS * DIM];
__device__ float g_V[M_ROWS * DIM];
__device__ float g_A[M_ROWS * DIM];

typedef unsigned long long u64;

__device__ __forceinline__ u64 pk2(float x, float y) {
    u64 r;
    asm("mov.b64 %0, {%1, %2};" : "=l"(r) : "f"(x), "f"(y));
    return r;
}
__device__ __forceinline__ void unpk2(u64 a, float& x, float& y) {
    asm("mov.b64 {%0, %1}, %2;" : "=f"(x), "=f"(y) : "l"(a));
}
// Packed dual-fp32 FMA (sm_100+): 2x FFMA throughput vs FFMA-3reg on B300.
__device__ __forceinline__ u64 fma2(u64 a, u64 b, u64 c) {
    u64 d;
    asm("fma.rn.f32x2 %0, %1, %2, %3;" : "=l"(d) : "l"(a), "l"(b), "l"(c));
    return d;
}

// C[M,1024] = A[M,1024] @ W[1024,1024] + bias
// 128x128 block tile, BK=16, 256 threads, 8x8 per-thread micro-tile.
// grid = (8 n-tiles, 256 m-tiles)
__global__ __launch_bounds__(256, 2)
void sgemm_bias(const float* __restrict__ A, const float* __restrict__ W,
                const float* __restrict__ bias, float* __restrict__ C)
{
    __shared__ float As[16][132];  // [k][m], padded: 132*4=528B row stride (16B aligned)
    __shared__ float Bs[16][132];  // [k][n]

    const int tid = threadIdx.x;
    const int tx = tid & 15;   // n micro index
    const int ty = tid >> 4;   // m micro index
    const int rowBase = blockIdx.y * 128;
    const int colBase = blockIdx.x * 128;

    u64 acc[8][4];
#pragma unroll
    for (int i = 0; i < 8; i++)
#pragma unroll
        for (int j = 0; j < 4; j++) acc[i][j] = 0ull;  // bit pattern 0 == (0.f,0.f)

    // Load index precompute (2 iterations of 256 threads each)
    // A tile: 512 float4 = 128 rows x 4 float4/row
    // B tile: 512 float4 = 16 k-rows x 32 float4/row
    float4 ra[2], rb[2];

    // --- initial tile (k0 = 0) ---
#pragma unroll
    for (int i = 0; i < 2; i++) {
        int idx = i * 256 + tid;
        int arow = idx >> 2, ak4 = (idx & 3) << 2;
        ra[i] = *(const float4*)(A + (size_t)(rowBase + arow) * DIM + ak4);
        int bk = idx >> 5, bc4 = (idx & 31) << 2;
        rb[i] = *(const float4*)(W + (size_t)bk * DIM + colBase + bc4);
    }
#pragma unroll
    for (int i = 0; i < 2; i++) {
        int idx = i * 256 + tid;
        int arow = idx >> 2, ak4 = (idx & 3) << 2;
        As[ak4 + 0][arow] = ra[i].x;
        As[ak4 + 1][arow] = ra[i].y;
        As[ak4 + 2][arow] = ra[i].z;
        As[ak4 + 3][arow] = ra[i].w;
        int bk = idx >> 5, bc4 = (idx & 31) << 2;
        *(float4*)&Bs[bk][bc4] = rb[i];
    }
    __syncthreads();

    for (int k0 = 0; k0 < DIM; k0 += 16) {
        const bool has_next = (k0 + 16 < DIM);
        if (has_next) {
#pragma unroll
            for (int i = 0; i < 2; i++) {
                int idx = i * 256 + tid;
                int arow = idx >> 2, ak4 = (idx & 3) << 2;
                ra[i] = *(const float4*)(A + (size_t)(rowBase + arow) * DIM + (k0 + 16) + ak4);
                int bk = idx >> 5, bc4 = (idx & 31) << 2;
                rb[i] = *(const float4*)(W + (size_t)(k0 + 16 + bk) * DIM + colBase + bc4);
            }
        }

#pragma unroll
        for (int k = 0; k < 16; k++) {
            float4 a0 = *(const float4*)&As[k][ty * 8];
            float4 a1 = *(const float4*)&As[k][ty * 8 + 4];
            u64 b[4];
            b[0] = *(const u64*)&Bs[k][tx * 8 + 0];
            b[1] = *(const u64*)&Bs[k][tx * 8 + 2];
            b[2] = *(const u64*)&Bs[k][tx * 8 + 4];
            b[3] = *(const u64*)&Bs[k][tx * 8 + 6];
            float av[8] = {a0.x, a0.y, a0.z, a0.w, a1.x, a1.y, a1.z, a1.w};
#pragma unroll
            for (int i = 0; i < 8; i++) {
                u64 ad = pk2(av[i], av[i]);
#pragma unroll
                for (int j = 0; j < 4; j++) acc[i][j] = fma2(ad, b[j], acc[i][j]);
            }
        }
        __syncthreads();

        if (has_next) {
#pragma unroll
            for (int i = 0; i < 2; i++) {
                int idx = i * 256 + tid;
                int arow = idx >> 2, ak4 = (idx & 3) << 2;
                As[ak4 + 0][arow] = ra[i].x;
                As[ak4 + 1][arow] = ra[i].y;
                As[ak4 + 2][arow] = ra[i].z;
                As[ak4 + 3][arow] = ra[i].w;
                int bk = idx >> 5, bc4 = (idx & 31) << 2;
                *(float4*)&Bs[bk][bc4] = rb[i];
            }
            __syncthreads();
        }
    }

    // Epilogue: add bias, store
    float bl[8];
#pragma unroll
    for (int j = 0; j < 8; j++) bl[j] = bias[colBase + tx * 8 + j];
#pragma unroll
    for (int i = 0; i < 8; i++) {
        int r = rowBase + ty * 8 + i;
        float* cRow = C + (size_t)r * DIM + colBase + tx * 8;
#pragma unroll
        for (int j = 0; j < 4; j++) {
            float x, y;
            unpk2(acc[i][j], x, y);
            float2 o = make_float2(x + bl[2 * j], y + bl[2 * j + 1]);
            *(float2*)&cRow[2 * j] = o;
        }
    }
}

// Per-node head-head attention: one block (128 threads) per node.
// scores[h][g] = (q_h . k_g) / 16 ; softmax over g ; attended_h = sum_g w[h][g] v_g
__global__ __launch_bounds__(128)
void attn_kernel(const float* __restrict__ Q, const float* __restrict__ K,
                 const float* __restrict__ V, float* __restrict__ Att)
{
    __shared__ float sq[DIM], sk[DIM], sv[DIM];
    __shared__ float sw[NH][NH];

    const int node = blockIdx.x;
    const int tid = threadIdx.x;
    const float* q = Q + (size_t)node * DIM;
    const float* k = K + (size_t)node * DIM;
    const float* v = V + (size_t)node * DIM;

#pragma unroll
    for (int i = tid; i < DIM / 4; i += 128) {
        ((float4*)sq)[i] = ((const float4*)q)[i];
        ((float4*)sk)[i] = ((const float4*)k)[i];
        ((float4*)sv)[i] = ((const float4*)v)[i];
    }
    __syncthreads();

    const int warp = tid >> 5, lane = tid & 31;
    // 16 (h,g) pairs over 4 warps: 4 pairs per warp
#pragma unroll
    for (int p = warp * 4; p < warp * 4 + 4; p++) {
        int h = p >> 2, g = p & 3;
        float s = 0.f;
#pragma unroll
        for (int e = lane; e < HD; e += 32) s += sq[h * HD + e] * sk[g * HD + e];
#pragma unroll
        for (int off = 16; off; off >>= 1) s += __shfl_xor_sync(0xffffffffu, s, off);
        if (lane == 0) sw[h][g] = s * 0.0625f;  // 1/sqrt(256)
    }
    __syncthreads();

    if (tid < NH) {
        float s0 = sw[tid][0], s1 = sw[tid][1], s2 = sw[tid][2], s3 = sw[tid][3];
        float m = fmaxf(fmaxf(s0, s1), fmaxf(s2, s3));
        float e0 = __expf(s0 - m), e1 = __expf(s1 - m), e2 = __expf(s2 - m), e3 = __expf(s3 - m);
        float inv = 1.f / (e0 + e1 + e2 + e3);
        sw[tid][0] = e0 * inv;
        sw[tid][1] = e1 * inv;
        sw[tid][2] = e2 * inv;
        sw[tid][3] = e3 * inv;
    }
    __syncthreads();

    float* a = Att + (size_t)node * DIM;
#pragma unroll
    for (int idx = tid; idx < DIM; idx += 128) {
        int h = idx >> 8, d = idx & 255;
        float s = sw[h][0] * sv[d] + sw[h][1] * sv[HD + d] +
                  sw[h][2] * sv[2 * HD + d] + sw[h][3] * sv[3 * HD + d];
        a[idx] = s;
    }
}

extern "C" void kernel_launch(void* const* d_in, const int* in_sizes, int n_in,
                              void* d_out, int out_size)
{
    const float* x  = (const float*)d_in[0];
    // d_in[1] = edge_index (int64) — unused by the reference computation
    const float* Wq = (const float*)d_in[2];
    const float* bq = (const float*)d_in[3];
    const float* Wk = (const float*)d_in[4];
    const float* bk = (const float*)d_in[5];
    const float* Wv = (const float*)d_in[6];
    const float* bv = (const float*)d_in[7];
    const float* Wo = (const float*)d_in[8];
    const float* bo = (const float*)d_in[9];
    float* out = (float*)d_out;

    float *Qp, *Kp, *Vp, *Ap;
    cudaGetSymbolAddress((void**)&Qp, g_Q);
    cudaGetSymbolAddress((void**)&Kp, g_K);
    cudaGetSymbolAddress((void**)&Vp, g_V);
    cudaGetSymbolAddress((void**)&Ap, g_A);

    dim3 grid(DIM / 128, M_ROWS / 128);  // (8, 256)
    sgemm_bias<<<grid, 256>>>(x, Wq, bq, Qp);
    sgemm_bias<<<grid, 256>>>(x, Wk, bk, Kp);
    sgemm_bias<<<grid, 256>>>(x, Wv, bv, Vp);
    attn_kernel<<<M_ROWS, 128>>>(Qp, Kp, Vp, Ap);
    sgemm_bias<<<grid, 256>>>(Ap, Wo, bo, out);
}

// round 4
// speedup vs baseline: 5.8694x; 5.8694x over previous
#include <cuda_runtime.h>
#include <cuda_fp16.h>
#include <cstdint>

#define M_ROWS (8 * 4096)
#define DIM 1024
#define NH 4
#define HD 256

#define BM 128
#define BN 128
#define BK 32
#define STAGES 4
#define KITERS (DIM / BK)          // 32
#define STAGE_BYTES 20480          // A 10240 + B 10240 (80B padded rows)
#define GEMM_SMEM (STAGES * STAGE_BYTES)

// ---------------- scratch (static device arrays; no allocation) -------------
__device__ __half g_xh[(size_t)M_ROWS * DIM];
__device__ __half g_qh[(size_t)M_ROWS * DIM];
__device__ __half g_kh[(size_t)M_ROWS * DIM];
__device__ __half g_vh[(size_t)M_ROWS * DIM];
__device__ __half g_ah[(size_t)M_ROWS * DIM];
__device__ __half g_wT[4][(size_t)DIM * DIM];

// ---------------- PTX helpers ------------------------------------------------
__device__ __forceinline__ uint32_t smem_u32(const void* p) {
    uint32_t a;
    asm("{ .reg .u64 t; cvta.to.shared.u64 t, %1; cvt.u32.u64 %0, t; }" : "=r"(a) : "l"(p));
    return a;
}
#define CP16(dst, src) \
    asm volatile("cp.async.cg.shared.global [%0], [%1], 16;" :: "r"(dst), "l"(src))
#define CP_COMMIT() asm volatile("cp.async.commit_group;" ::: "memory")
#define CP_WAIT2()  asm volatile("cp.async.wait_group 2;" ::: "memory")

#define LDSM_X4(r, addr) \
    asm volatile("ldmatrix.sync.aligned.m8n8.x4.shared.b16 {%0,%1,%2,%3}, [%4];" \
        : "=r"((r)[0]), "=r"((r)[1]), "=r"((r)[2]), "=r"((r)[3]) : "r"(addr))

#define MMA16816(d, a, b) \
    asm volatile("mma.sync.aligned.m16n8k16.row.col.f32.f16.f16.f32 " \
        "{%0,%1,%2,%3}, {%4,%5,%6,%7}, {%8,%9}, {%0,%1,%2,%3};" \
        : "+f"((d)[0]), "+f"((d)[1]), "+f"((d)[2]), "+f"((d)[3]) \
        : "r"((a)[0]), "r"((a)[1]), "r"((a)[2]), "r"((a)[3]), "r"((b)[0]), "r"((b)[1]))

// ---------------- fp16 GEMM via mma.sync -------------------------------------
// C[M,1024] = A[M,1024] @ B^T + bias, A fp16 row-major, B stored [N][K] fp16.
// OUT_HALF ? C fp16 : C fp32.  grid = (8, 256), 256 threads.
template <bool OUT_HALF>
__global__ void __launch_bounds__(256, 2)
gemm_h(const __half* __restrict__ A, const __half* __restrict__ B,
       const float* __restrict__ bias, void* __restrict__ Cv)
{
    extern __shared__ char sm[];
    const uint32_t sbase = smem_u32(sm);

    const int tid = threadIdx.x;
    const int wid = tid >> 5, lane = tid & 31;
    const int warp_m = wid & 1;        // 2 warps over M (64 rows each)
    const int warp_n = wid >> 1;       // 4 warps over N (32 cols each)
    const int rowBase = blockIdx.y * BM;
    const int colBase = blockIdx.x * BN;

    // cp.async indices: 512 16B-chunks per operand tile; this thread owns
    // chunk tid and tid+256. chunk -> (row = c/4, seg = c%4).
    const int r0 = tid >> 2, c0 = tid & 3;
    const __half* gA = A + (size_t)(rowBase + r0) * DIM + c0 * 8;
    const __half* gB = B + (size_t)(colBase + r0) * DIM + c0 * 8;
    const uint32_t sOffA = (uint32_t)(r0 * 80 + c0 * 16);

    float acc[4][4][4];
#pragma unroll
    for (int i = 0; i < 4; i++)
#pragma unroll
        for (int j = 0; j < 4; j++)
#pragma unroll
            for (int q = 0; q < 4; q++) acc[i][j][q] = 0.f;

    auto prefetch = [&](int s, int k0) {
        uint32_t sA = sbase + s * STAGE_BYTES;
        uint32_t sB = sA + 10240;
        const __half* pa = gA + k0;
        const __half* pb = gB + k0;
        CP16(sA + sOffA, pa);
        CP16(sA + sOffA + 64 * 80, pa + (size_t)64 * DIM);
        CP16(sB + sOffA, pb);
        CP16(sB + sOffA + 64 * 80, pb + (size_t)64 * DIM);
        CP_COMMIT();
    };

#pragma unroll
    for (int s = 0; s < STAGES - 1; s++) prefetch(s, s * BK);

    // ldmatrix base addresses (per-warp, per-lane)
    const uint32_t aLane = (uint32_t)((warp_m * 64 + (lane & 15)) * 80 + (lane >> 4) * 16);
    const uint32_t bLane = (uint32_t)((warp_n * 32 + (lane & 7) + ((lane >> 4) << 3)) * 80 +
                                      ((lane >> 3) & 1) * 16);

    for (int i = 0; i < KITERS; i++) {
        CP_WAIT2();
        __syncthreads();
        if (i + STAGES - 1 < KITERS) prefetch((i + STAGES - 1) & (STAGES - 1), (i + STAGES - 1) * BK);
        else CP_COMMIT();

        const uint32_t st = sbase + (i & (STAGES - 1)) * STAGE_BYTES;
        const uint32_t aB = st + aLane;
        const uint32_t bB = st + 10240 + bLane;
#pragma unroll
        for (int kk = 0; kk < 2; kk++) {
            uint32_t af[4][4], bf[2][4];
#pragma unroll
            for (int mt = 0; mt < 4; mt++) LDSM_X4(af[mt], aB + mt * 16 * 80 + kk * 32);
#pragma unroll
            for (int p = 0; p < 2; p++) LDSM_X4(bf[p], bB + p * 16 * 80 + kk * 32);
#pragma unroll
            for (int mt = 0; mt < 4; mt++)
#pragma unroll
                for (int nt = 0; nt < 4; nt++)
                    MMA16816(acc[mt][nt], af[mt], bf[nt >> 1] + (nt & 1) * 2);
        }
    }

    // epilogue
#pragma unroll
    for (int mt = 0; mt < 4; mt++) {
        const int row = rowBase + warp_m * 64 + mt * 16 + (lane >> 2);
#pragma unroll
        for (int nt = 0; nt < 4; nt++) {
            const int col = colBase + warp_n * 32 + nt * 8 + (lane & 3) * 2;
            const float bx = bias[col], by = bias[col + 1];
            if (OUT_HALF) {
                __half* C = (__half*)Cv;
                *(__half2*)(C + (size_t)row * DIM + col) =
                    __floats2half2_rn(acc[mt][nt][0] + bx, acc[mt][nt][1] + by);
                *(__half2*)(C + (size_t)(row + 8) * DIM + col) =
                    __floats2half2_rn(acc[mt][nt][2] + bx, acc[mt][nt][3] + by);
            } else {
                float* C = (float*)Cv;
                *(float2*)(C + (size_t)row * DIM + col) =
                    make_float2(acc[mt][nt][0] + bx, acc[mt][nt][1] + by);
                *(float2*)(C + (size_t)(row + 8) * DIM + col) =
                    make_float2(acc[mt][nt][2] + bx, acc[mt][nt][3] + by);
            }
        }
    }
}

// ---------------- conversion kernels -----------------------------------------
__global__ void cvt_f2h(const float4* __restrict__ in, uint2* __restrict__ out, int n4)
{
    for (int i = blockIdx.x * blockDim.x + threadIdx.x; i < n4; i += gridDim.x * blockDim.x) {
        float4 v = in[i];
        __half2 h01 = __floats2half2_rn(v.x, v.y);
        __half2 h23 = __floats2half2_rn(v.z, v.w);
        out[i] = make_uint2(*(uint32_t*)&h01, *(uint32_t*)&h23);
    }
}

// W[K][N] f32 -> WT[N][K] fp16
__global__ void cvt_wT(const float* __restrict__ W, __half* __restrict__ T)
{
    __shared__ float tile[32][33];
    int n0 = blockIdx.x * 32, k0 = blockIdx.y * 32;
    int tx = threadIdx.x, ty = threadIdx.y;
#pragma unroll
    for (int j = 0; j < 32; j += 8)
        tile[ty + j][tx] = W[(size_t)(k0 + ty + j) * DIM + n0 + tx];
    __syncthreads();
#pragma unroll
    for (int j = 0; j < 32; j += 8)
        T[(size_t)(n0 + ty + j) * DIM + k0 + tx] = __float2half_rn(tile[tx][ty + j]);
}

// ---------------- per-node head-head attention (fp16 in / fp16 out) ----------
__global__ __launch_bounds__(128)
void attn_kernel(const __half* __restrict__ Q, const __half* __restrict__ K,
                 const __half* __restrict__ V, __half* __restrict__ Ah)
{
    __shared__ float sq[DIM], sk[DIM], sv[DIM];
    __shared__ float sw[NH][NH];

    const int node = blockIdx.x;
    const int tid = threadIdx.x;
    const __half* q = Q + (size_t)node * DIM;
    const __half* k = K + (size_t)node * DIM;
    const __half* v = V + (size_t)node * DIM;

    {
        uint4 vq = ((const uint4*)q)[tid];
        uint4 vk = ((const uint4*)k)[tid];
        uint4 vv = ((const uint4*)v)[tid];
        const __half2* hq = (const __half2*)&vq;
        const __half2* hk = (const __half2*)&vk;
        const __half2* hv = (const __half2*)&vv;
#pragma unroll
        for (int j = 0; j < 4; j++) {
            float2 fq = __half22float2(hq[j]);
            float2 fk = __half22float2(hk[j]);
            float2 fv = __half22float2(hv[j]);
            sq[tid * 8 + 2 * j] = fq.x; sq[tid * 8 + 2 * j + 1] = fq.y;
            sk[tid * 8 + 2 * j] = fk.x; sk[tid * 8 + 2 * j + 1] = fk.y;
            sv[tid * 8 + 2 * j] = fv.x; sv[tid * 8 + 2 * j + 1] = fv.y;
        }
    }
    __syncthreads();

    const int warp = tid >> 5, lane = tid & 31;
#pragma unroll
    for (int p = warp * 4; p < warp * 4 + 4; p++) {
        int h = p >> 2, g = p & 3;
        float s = 0.f;
#pragma unroll
        for (int e = lane; e < HD; e += 32) s += sq[h * HD + e] * sk[g * HD + e];
#pragma unroll
        for (int off = 16; off; off >>= 1) s += __shfl_xor_sync(0xffffffffu, s, off);
        if (lane == 0) sw[h][g] = s * 0.0625f;
    }
    __syncthreads();

    if (tid < NH) {
        float s0 = sw[tid][0], s1 = sw[tid][1], s2 = sw[tid][2], s3 = sw[tid][3];
        float m = fmaxf(fmaxf(s0, s1), fmaxf(s2, s3));
        float e0 = __expf(s0 - m), e1 = __expf(s1 - m), e2 = __expf(s2 - m), e3 = __expf(s3 - m);
        float inv = 1.f / (e0 + e1 + e2 + e3);
        sw[tid][0] = e0 * inv; sw[tid][1] = e1 * inv;
        sw[tid][2] = e2 * inv; sw[tid][3] = e3 * inv;
    }
    __syncthreads();

    size_t base = (size_t)node * DIM;
#pragma unroll
    for (int idx = tid; idx < DIM; idx += 128) {
        int h = idx >> 8, d = idx & 255;
        float s = sw[h][0] * sv[d] + sw[h][1] * sv[HD + d] +
                  sw[h][2] * sv[2 * HD + d] + sw[h][3] * sv[3 * HD + d];
        Ah[base + idx] = __float2half_rn(s);
    }
}

// ---------------- launch -----------------------------------------------------
extern "C" void kernel_launch(void* const* d_in, const int* in_sizes, int n_in,
                              void* d_out, int out_size)
{
    const float* x  = (const float*)d_in[0];
    const float* Wq = (const float*)d_in[2];
    const float* bq = (const float*)d_in[3];
    const float* Wk = (const float*)d_in[4];
    const float* bk = (const float*)d_in[5];
    const float* Wv = (const float*)d_in[6];
    const float* bv = (const float*)d_in[7];
    const float* Wo = (const float*)d_in[8];
    const float* bo = (const float*)d_in[9];
    float* out = (float*)d_out;

    __half *xh, *qh, *kh, *vh, *ah, *wT;
    cudaGetSymbolAddress((void**)&xh, g_xh);
    cudaGetSymbolAddress((void**)&qh, g_qh);
    cudaGetSymbolAddress((void**)&kh, g_kh);
    cudaGetSymbolAddress((void**)&vh, g_vh);
    cudaGetSymbolAddress((void**)&ah, g_ah);
    cudaGetSymbolAddress((void**)&wT, g_wT);

    cudaFuncSetAttribute(gemm_h<true>,  cudaFuncAttributeMaxDynamicSharedMemorySize, GEMM_SMEM);
    cudaFuncSetAttribute(gemm_h<false>, cudaFuncAttributeMaxDynamicSharedMemorySize, GEMM_SMEM);

    const size_t WSZ = (size_t)DIM * DIM;

    cvt_f2h<<<2048, 256>>>((const float4*)x, (uint2*)xh, M_ROWS * DIM / 4);
    dim3 tgrid(32, 32), tblk(32, 8);
    cvt_wT<<<tgrid, tblk>>>(Wq, wT + 0 * WSZ);
    cvt_wT<<<tgrid, tblk>>>(Wk, wT + 1 * WSZ);
    cvt_wT<<<tgrid, tblk>>>(Wv, wT + 2 * WSZ);
    cvt_wT<<<tgrid, tblk>>>(Wo, wT + 3 * WSZ);

    dim3 ggrid(DIM / BN, M_ROWS / BM);  // (8, 256)
    gemm_h<true><<<ggrid, 256, GEMM_SMEM>>>(xh, wT + 0 * WSZ, bq, qh);
    gemm_h<true><<<ggrid, 256, GEMM_SMEM>>>(xh, wT + 1 * WSZ, bk, kh);
    gemm_h<true><<<ggrid, 256, GEMM_SMEM>>>(xh, wT + 2 * WSZ, bv, vh);
    attn_kernel<<<M_ROWS, 128>>>(qh, kh, vh, ah);
    gemm_h<false><<<ggrid, 256, GEMM_SMEM>>>(ah, wT + 3 * WSZ, bo, out);
}